// round 9
// baseline (speedup 1.0000x reference)
#include <cuda_runtime.h>
#include <cuda_bf16.h>
#include <cuda_fp16.h>
#include <math.h>

// ---------------- static config ----------------
#define HWP   4096
#define PP    32768
#define DIMC  256
#define CRC   64
#define GCC   32
#define HCC   16
#define N9    9
#define OFFC  18
#define NCLS  80
#define SCALEF 0.25f
#define MULF  5.0f

// ---------------- scratch ----------------
__device__ __nv_bfloat16 g_xnh[PP * DIMC];   // LN'd x, bf16 hi  [P,256]
__device__ __nv_bfloat16 g_xnl[PP * DIMC];   // LN'd x, bf16 lo
__device__ float  g_qbuf[PP * CRC];
__device__ __half g_kbufh[16 * HWP * GCC];
__device__ __half g_vbufh[16 * HWP * GCC];
__device__ float  g_tbuf[16 * HWP * GCC];
__device__ float  g_offbuf[16 * HWP * OFFC];
__device__ float  g_attnout[PP * CRC];
__device__ float  g_ybuf[PP * DIMC];

// ---------------- kernel 1: channel-LN + transpose + bf16 hi/lo split ----------
__global__ void k_ln(const float* __restrict__ x,
                     const float* __restrict__ gam,
                     const float* __restrict__ bet)
{
    __shared__ float s[DIMC][33];
    __shared__ float red[2][8][32];
    __shared__ float smean[32], srstd[32];

    int p0 = blockIdx.x * 32;
    int b  = p0 >> 12;
    int hw0 = p0 & 4095;
    int tid = threadIdx.x;
    int tx = tid & 31, ty = tid >> 5;

    const float* xb = x + (size_t)b * DIMC * HWP + hw0;
    for (int c = ty; c < DIMC; c += 8)
        s[c][tx] = xb[c * HWP + tx];
    __syncthreads();

    float sum = 0.f, sq = 0.f;
    for (int c = ty; c < DIMC; c += 8) {
        float v = s[c][tx];
        sum += v; sq += v * v;
    }
    red[0][ty][tx] = sum; red[1][ty][tx] = sq;
    __syncthreads();
    if (ty == 0) {
        float s1 = 0.f, s2 = 0.f;
        #pragma unroll
        for (int j = 0; j < 8; j++) { s1 += red[0][j][tx]; s2 += red[1][j][tx]; }
        float m = s1 * (1.f / 256.f);
        float v = s2 * (1.f / 256.f) - m * m;
        smean[tx] = m;
        srstd[tx] = rsqrtf(v + 1e-5f);
    }
    __syncthreads();

    float gg = gam[tid], bb = bet[tid];
    for (int pl = 0; pl < 32; pl++) {
        float v = (s[tid][pl] - smean[pl]) * srstd[pl] * gg + bb;
        __nv_bfloat16 h = __float2bfloat16(v);
        __nv_bfloat16 l = __float2bfloat16(v - __bfloat162float(h));
        size_t o = (size_t)(p0 + pl) * DIMC + tid;
        g_xnh[o] = h;
        g_xnl[o] = l;
    }
}

// ---------------- helpers ----------------
__device__ __forceinline__ void cvt_pair(float x0, float x1,
                                         unsigned& hi, unsigned& lo)
{
    __nv_bfloat16 h0 = __float2bfloat16(x0);
    __nv_bfloat16 h1 = __float2bfloat16(x1);
    float r0 = x0 - __bfloat162float(h0);
    float r1 = x1 - __bfloat162float(h1);
    __nv_bfloat16 l0 = __float2bfloat16(r0);
    __nv_bfloat16 l1 = __float2bfloat16(r1);
    unsigned short u0 = *(unsigned short*)&h0, u1 = *(unsigned short*)&h1;
    unsigned short v0 = *(unsigned short*)&l0, v1 = *(unsigned short*)&l1;
    hi = (unsigned)u0 | ((unsigned)u1 << 16);
    lo = (unsigned)v0 | ((unsigned)v1 << 16);
}

__device__ __forceinline__ void mma_bf16_v(float* c,
                                           unsigned a0, unsigned a1, unsigned a2, unsigned a3,
                                           unsigned b0, unsigned b1)
{
    asm volatile(
        "mma.sync.aligned.m16n8k16.row.col.f32.bf16.bf16.f32 "
        "{%0,%1,%2,%3}, {%4,%5,%6,%7}, {%8,%9}, {%0,%1,%2,%3};\n"
        : "+f"(c[0]), "+f"(c[1]), "+f"(c[2]), "+f"(c[3])
        : "r"(a0), "r"(a1), "r"(a2), "r"(a3), "r"(b0), "r"(b1));
}
#define MMA_BF16 mma_bf16_v

// ---------------- GEMM 0: qkv from pre-split A ------------------------------
__global__ void __launch_bounds__(256) k_gemm0(const float* __restrict__ Bw)
{
    constexpr int K = 256, Ntot = 192;

    __shared__ unsigned Ah[128][20], Al[128][20];
    __shared__ unsigned Bh[64][20],  Bl[64][20];

    int tid = threadIdx.x;
    int lane = tid & 31;
    int warpId = tid >> 5;
    int warpM = warpId & 3;
    int warpN = warpId >> 2;
    int row0 = blockIdx.y * 128, col0 = blockIdx.x * 64;

    float acc[2][4][4];
    #pragma unroll
    for (int mt = 0; mt < 2; mt++)
        #pragma unroll
        for (int nt = 0; nt < 4; nt++)
            #pragma unroll
            for (int e = 0; e < 4; e++) acc[mt][nt][e] = 0.f;

    uint4 ph[2], pl[2];
    float4 pb[2];

    #pragma unroll
    for (int i = 0; i < 2; i++) {
        int id = tid + i * 256;
        int row = id >> 2, fq = id & 3;
        ph[i] = *(const uint4*)(g_xnh + (size_t)(row0 + row) * K + fq * 8);
        pl[i] = *(const uint4*)(g_xnl + (size_t)(row0 + row) * K + fq * 8);
        int brow = id >> 3, bf = id & 7;
        pb[i] = make_float4(0.f, 0.f, 0.f, 0.f);
        if (col0 + brow < Ntot)
            pb[i] = *(const float4*)(Bw + (size_t)(col0 + brow) * K + bf * 4);
    }

    for (int k0 = 0; k0 < K; k0 += 32) {
        #pragma unroll
        for (int i = 0; i < 2; i++) {
            int id = tid + i * 256;
            int row = id >> 2, fq = id & 3;
            *(uint4*)&Ah[row][fq * 4] = ph[i];
            *(uint4*)&Al[row][fq * 4] = pl[i];
            int brow = id >> 3, bf = id & 7;
            unsigned h0, l0, h1, l1;
            float4 v = pb[i];
            cvt_pair(v.x, v.y, h0, l0);
            cvt_pair(v.z, v.w, h1, l1);
            Bh[brow][bf * 2] = h0; Bh[brow][bf * 2 + 1] = h1;
            Bl[brow][bf * 2] = l0; Bl[brow][bf * 2 + 1] = l1;
        }
        __syncthreads();

        if (k0 + 32 < K) {
            #pragma unroll
            for (int i = 0; i < 2; i++) {
                int id = tid + i * 256;
                int row = id >> 2, fq = id & 3;
                ph[i] = *(const uint4*)(g_xnh + (size_t)(row0 + row) * K + (k0 + 32) + fq * 8);
                pl[i] = *(const uint4*)(g_xnl + (size_t)(row0 + row) * K + (k0 + 32) + fq * 8);
                int brow = id >> 3, bf = id & 7;
                pb[i] = make_float4(0.f, 0.f, 0.f, 0.f);
                if (col0 + brow < Ntot)
                    pb[i] = *(const float4*)(Bw + (size_t)(col0 + brow) * K + (k0 + 32) + bf * 4);
            }
        }

        #pragma unroll
        for (int kk = 0; kk < 2; kk++) {
            int kb = kk * 8 + (lane & 3);
            unsigned ah[2][4], al[2][4];
            #pragma unroll
            for (int mt = 0; mt < 2; mt++) {
                int ar = warpM * 32 + mt * 16 + (lane >> 2);
                ah[mt][0] = Ah[ar][kb];     ah[mt][1] = Ah[ar + 8][kb];
                ah[mt][2] = Ah[ar][kb + 4]; ah[mt][3] = Ah[ar + 8][kb + 4];
                al[mt][0] = Al[ar][kb];     al[mt][1] = Al[ar + 8][kb];
                al[mt][2] = Al[ar][kb + 4]; al[mt][3] = Al[ar + 8][kb + 4];
            }
            #pragma unroll
            for (int nt = 0; nt < 4; nt++) {
                int br = warpN * 32 + nt * 8 + (lane >> 2);
                unsigned bh0 = Bh[br][kb], bh1 = Bh[br][kb + 4];
                unsigned bl0 = Bl[br][kb], bl1 = Bl[br][kb + 4];
                #pragma unroll
                for (int mt = 0; mt < 2; mt++) {
                    MMA_BF16(acc[mt][nt], ah[mt][0], ah[mt][1], ah[mt][2], ah[mt][3], bh0, bh1);
                    MMA_BF16(acc[mt][nt], ah[mt][0], ah[mt][1], ah[mt][2], ah[mt][3], bl0, bl1);
                    MMA_BF16(acc[mt][nt], al[mt][0], al[mt][1], al[mt][2], al[mt][3], bh0, bh1);
                }
            }
        }
        __syncthreads();
    }

    #pragma unroll
    for (int mt = 0; mt < 2; mt++) {
        #pragma unroll
        for (int nt = 0; nt < 4; nt++) {
            #pragma unroll
            for (int e = 0; e < 4; e++) {
                int p = row0 + warpM * 32 + mt * 16 + (lane >> 2) + ((e >= 2) ? 8 : 0);
                int o = col0 + warpN * 32 + nt * 8 + 2 * (lane & 3) + (e & 1);
                float v = acc[mt][nt][e];
                int bidx = p >> 12, hw = p & 4095;
                if (o < 64) {
                    g_qbuf[p * 64 + o] = v;
                } else if (o < 128) {
                    int c = o - 64;
                    g_kbufh[((size_t)(bidx * 2 + (c >> 5)) * HWP + hw) * GCC + (c & 31)] =
                        __float2half(v);
                } else {
                    int c = o - 128;
                    g_vbufh[((size_t)(bidx * 2 + (c >> 5)) * HWP + hw) * GCC + (c & 31)] =
                        __float2half(v);
                }
            }
        }
    }
}

// ---------------- GEMM modes 1/2 (fp32 A, cvt staging + prefetch) --------------
template<int MODE>
__global__ void __launch_bounds__(256) k_gemm(const float* __restrict__ Bw,
                                              const float* __restrict__ bias,
                                              const float* __restrict__ resid,
                                              float* __restrict__ outp)
{
    constexpr int K    = (MODE == 1) ? 64 : 256;
    constexpr int Ntot = (MODE == 1) ? 256 : 80;
    const float* A = (MODE == 1) ? g_attnout : g_ybuf;

    __shared__ unsigned Ah[128][20], Al[128][20];
    __shared__ unsigned Bh[64][20],  Bl[64][20];

    int tid = threadIdx.x;
    int lane = tid & 31;
    int warpId = tid >> 5;
    int warpM = warpId & 3;
    int warpN = warpId >> 2;
    int row0 = blockIdx.y * 128, col0 = blockIdx.x * 64;

    float acc[2][4][4];
    #pragma unroll
    for (int mt = 0; mt < 2; mt++)
        #pragma unroll
        for (int nt = 0; nt < 4; nt++)
            #pragma unroll
            for (int e = 0; e < 4; e++) acc[mt][nt][e] = 0.f;

    float4 pa[4], pb[2];
    #pragma unroll
    for (int i = 0; i < 4; i++) {
        int id = tid + i * 256;
        int row = id >> 3, f = id & 7;
        pa[i] = *(const float4*)(A + (size_t)(row0 + row) * K + f * 4);
    }
    #pragma unroll
    for (int i = 0; i < 2; i++) {
        int id = tid + i * 256;
        int row = id >> 3, f = id & 7;
        pb[i] = make_float4(0.f, 0.f, 0.f, 0.f);
        if (col0 + row < Ntot)
            pb[i] = *(const float4*)(Bw + (size_t)(col0 + row) * K + f * 4);
    }

    for (int k0 = 0; k0 < K; k0 += 32) {
        #pragma unroll
        for (int i = 0; i < 4; i++) {
            int id = tid + i * 256;
            int row = id >> 3, f = id & 7;
            unsigned h0, l0, h1, l1;
            cvt_pair(pa[i].x, pa[i].y, h0, l0);
            cvt_pair(pa[i].z, pa[i].w, h1, l1);
            Ah[row][f * 2] = h0; Ah[row][f * 2 + 1] = h1;
            Al[row][f * 2] = l0; Al[row][f * 2 + 1] = l1;
        }
        #pragma unroll
        for (int i = 0; i < 2; i++) {
            int id = tid + i * 256;
            int row = id >> 3, f = id & 7;
            unsigned h0, l0, h1, l1;
            cvt_pair(pb[i].x, pb[i].y, h0, l0);
            cvt_pair(pb[i].z, pb[i].w, h1, l1);
            Bh[row][f * 2] = h0; Bh[row][f * 2 + 1] = h1;
            Bl[row][f * 2] = l0; Bl[row][f * 2 + 1] = l1;
        }
        __syncthreads();

        if (k0 + 32 < K) {
            #pragma unroll
            for (int i = 0; i < 4; i++) {
                int id = tid + i * 256;
                int row = id >> 3, f = id & 7;
                pa[i] = *(const float4*)(A + (size_t)(row0 + row) * K + (k0 + 32) + f * 4);
            }
            #pragma unroll
            for (int i = 0; i < 2; i++) {
                int id = tid + i * 256;
                int row = id >> 3, f = id & 7;
                pb[i] = make_float4(0.f, 0.f, 0.f, 0.f);
                if (col0 + row < Ntot)
                    pb[i] = *(const float4*)(Bw + (size_t)(col0 + row) * K + (k0 + 32) + f * 4);
            }
        }

        #pragma unroll
        for (int kk = 0; kk < 2; kk++) {
            int kb = kk * 8 + (lane & 3);
            unsigned ah[2][4], al[2][4];
            #pragma unroll
            for (int mt = 0; mt < 2; mt++) {
                int ar = warpM * 32 + mt * 16 + (lane >> 2);
                ah[mt][0] = Ah[ar][kb];     ah[mt][1] = Ah[ar + 8][kb];
                ah[mt][2] = Ah[ar][kb + 4]; ah[mt][3] = Ah[ar + 8][kb + 4];
                al[mt][0] = Al[ar][kb];     al[mt][1] = Al[ar + 8][kb];
                al[mt][2] = Al[ar][kb + 4]; al[mt][3] = Al[ar + 8][kb + 4];
            }
            #pragma unroll
            for (int nt = 0; nt < 4; nt++) {
                int br = warpN * 32 + nt * 8 + (lane >> 2);
                unsigned bh0 = Bh[br][kb], bh1 = Bh[br][kb + 4];
                unsigned bl0 = Bl[br][kb], bl1 = Bl[br][kb + 4];
                #pragma unroll
                for (int mt = 0; mt < 2; mt++) {
                    MMA_BF16(acc[mt][nt], ah[mt][0], ah[mt][1], ah[mt][2], ah[mt][3], bh0, bh1);
                    MMA_BF16(acc[mt][nt], ah[mt][0], ah[mt][1], ah[mt][2], ah[mt][3], bl0, bl1);
                    MMA_BF16(acc[mt][nt], al[mt][0], al[mt][1], al[mt][2], al[mt][3], bh0, bh1);
                }
            }
        }
        __syncthreads();
    }

    #pragma unroll
    for (int mt = 0; mt < 2; mt++) {
        #pragma unroll
        for (int nt = 0; nt < 4; nt++) {
            #pragma unroll
            for (int e = 0; e < 4; e++) {
                int p = row0 + warpM * 32 + mt * 16 + (lane >> 2) + ((e >= 2) ? 8 : 0);
                int o = col0 + warpN * 32 + nt * 8 + 2 * (lane & 3) + (e & 1);
                float v = acc[mt][nt][e];
                int bidx = p >> 12, hw = p & 4095;
                if (MODE == 1) {
                    g_ybuf[(size_t)p * DIMC + o] =
                        v + bias[o] + resid[(size_t)bidx * DIMC * HWP + o * HWP + hw];
                } else {
                    if (o < Ntot)
                        outp[(size_t)bidx * NCLS * HWP + o * HWP + hw] = v + bias[o];
                }
            }
        }
    }
}

// ---------------- kernel 3: smem-tiled depthwise 3x3 + LN(32) + GELU ----------
__global__ void __launch_bounds__(256, 2) k_dw(const float* __restrict__ wdw,
                                               const float* __restrict__ g2,
                                               const float* __restrict__ b2)
{
    extern __shared__ float4 st4[];
    __shared__ float sw[GCC * 9];
    __shared__ float sg[GCC], sb[GCC];

    int bg = blockIdx.x >> 4;
    int h0 = (blockIdx.x & 15) * 4;
    int b = bg >> 1, g = bg & 1;
    int tid = threadIdx.x;

    for (int i = tid; i < GCC * 9; i += 256) sw[i] = wdw[i];
    if (tid < GCC) { sg[tid] = g2[tid]; sb[tid] = b2[tid]; }
    for (int i = tid; i < 3168; i += 256) st4[i] = make_float4(0.f, 0.f, 0.f, 0.f);
    __syncthreads();

    for (int i = tid; i < 3072; i += 256) {
        int c4 = i & 7, col = (i >> 3) & 63, r = i >> 9;
        int gr = h0 - 1 + r;
        if ((unsigned)gr < 64u)
            st4[(c4 * 6 + r) * 66 + col + 1] =
                *(const float4*)(g_qbuf + ((size_t)(b * HWP + gr * 64 + col)) * CRC + g * GCC + c4 * 4);
    }
    __syncthreads();

    int col = tid & 63;
    int row = tid >> 6;
    int h = h0 + row;

    float acc[GCC];
    #pragma unroll
    for (int c = 0; c < GCC; c++) acc[c] = 0.f;

    #pragma unroll
    for (int ky = 0; ky < 3; ky++) {
        #pragma unroll
        for (int kx = 0; kx < 3; kx++) {
            int kidx = ky * 3 + kx;
            #pragma unroll
            for (int c4 = 0; c4 < 8; c4++) {
                float4 v = st4[(c4 * 6 + row + ky) * 66 + col + kx];
                acc[c4 * 4 + 0] += v.x * sw[(c4 * 4 + 0) * 9 + kidx];
                acc[c4 * 4 + 1] += v.y * sw[(c4 * 4 + 1) * 9 + kidx];
                acc[c4 * 4 + 2] += v.z * sw[(c4 * 4 + 2) * 9 + kidx];
                acc[c4 * 4 + 3] += v.w * sw[(c4 * 4 + 3) * 9 + kidx];
            }
        }
    }

    float m = 0.f;
    #pragma unroll
    for (int c = 0; c < GCC; c++) m += acc[c];
    m *= (1.f / GCC);
    float v = 0.f;
    #pragma unroll
    for (int c = 0; c < GCC; c++) { float d = acc[c] - m; v += d * d; }
    float rs = rsqrtf(v * (1.f / GCC) + 1e-5f);

    float* dst = g_tbuf + ((size_t)bg * HWP + h * 64 + col) * GCC;
    #pragma unroll
    for (int c = 0; c < GCC; c++) {
        float t = (acc[c] - m) * rs * sg[c] + sb[c];
        dst[c] = 0.5f * t * (1.f + erff(t * 0.70710678118654752f));
    }
}

// ---------------- kernel 4: smem-tiled 3x3 conv (32->18), 2 rows/block --------
__global__ void __launch_bounds__(256) k_off(const float* __restrict__ woff,
                                             const float* __restrict__ boff,
                                             const float* __restrict__ offset)
{
    extern __shared__ float4 dyn4[];
    float4* st4 = dyn4;
    float*  sw  = (float*)(dyn4 + 2112);
    float4* sw4 = (float4*)sw;

    int bg = blockIdx.x >> 5;
    int h0 = (blockIdx.x & 31) * 2;
    int tid = threadIdx.x;

    for (int i = tid; i < OFFC * GCC * 9; i += 256) {
        int o = i / (GCC * 9); int rem = i - o * (GCC * 9);
        int c = rem / 9; int kidx = rem - c * 9;
        sw[(kidx * OFFC + o) * GCC + c] = woff[i];
    }
    for (int i = tid; i < 2112; i += 256) st4[i] = make_float4(0.f, 0.f, 0.f, 0.f);
    __syncthreads();

    for (int i = tid; i < 2048; i += 256) {
        int c4 = i & 7, col = (i >> 3) & 63, r = i >> 9;
        int gr = h0 - 1 + r;
        if ((unsigned)gr < 64u)
            st4[(c4 * 4 + r) * 66 + col + 1] =
                *(const float4*)(g_tbuf + ((size_t)(bg * HWP + gr * 64 + col)) * GCC + c4 * 4);
    }
    __syncthreads();

    int col = tid & 63;
    int og  = (tid >> 6) & 1;
    int row = tid >> 7;
    int h = h0 + row;
    int b = bg >> 1;

    float acc[9];
    #pragma unroll
    for (int o = 0; o < 9; o++) acc[o] = boff[og * 9 + o];

    #pragma unroll
    for (int c4 = 0; c4 < 8; c4++) {
        #pragma unroll
        for (int ky = 0; ky < 3; ky++) {
            const float4* trow = &st4[(c4 * 4 + row + ky) * 66];
            float4 t[3];
            t[0] = trow[col]; t[1] = trow[col + 1]; t[2] = trow[col + 2];
            #pragma unroll
            for (int kx = 0; kx < 3; kx++) {
                int kidx = ky * 3 + kx;
                #pragma unroll
                for (int o = 0; o < 9; o++) {
                    float4 w = sw4[(kidx * OFFC + og * 9 + o) * 8 + c4];
                    acc[o] += t[kx].x * w.x + t[kx].y * w.y +
                              t[kx].z * w.z + t[kx].w * w.w;
                }
            }
        }
    }

    int hw = h * 64 + col;
    const float* ofs = offset + (size_t)b * OFFC * HWP + hw;
    float* dst = g_offbuf + ((size_t)bg * HWP + hw) * OFFC + og * 9;
    #pragma unroll
    for (int o = 0; o < 9; o++)
        dst[o] = tanhf(acc[o]) * MULF + ofs[(og * 9 + o) * HWP];
}

// ---------------- kernel 5: deformable attention, 2 heads per thread -----------
// NOTE: a group line is 32 halfs = 64 bytes = FOUR uint4 (8 halfs each).
__device__ __forceinline__ void samp32(const __half* __restrict__ bufh,
                                       int y, int x, float w, float s[32])
{
    if ((unsigned)x < 64u && (unsigned)y < 64u) {
        const uint4* q = (const uint4*)(bufh + (y * 64 + x) * GCC);
        #pragma unroll
        for (int j = 0; j < 4; j++) {
            uint4 u = q[j];
            const __half2* h = (const __half2*)&u;
            #pragma unroll
            for (int i = 0; i < 4; i++) {
                float2 f = __half22float2(h[i]);
                s[j * 8 + 2 * i]     += w * f.x;
                s[j * 8 + 2 * i + 1] += w * f.y;
            }
        }
    }
}

__device__ __forceinline__ void samp32w2(const __half* __restrict__ bufh,
                                         int y, int x, float wA, float wB,
                                         float oA[16], float oB[16])
{
    if ((unsigned)x < 64u && (unsigned)y < 64u) {
        const uint4* q = (const uint4*)(bufh + (y * 64 + x) * GCC);
        uint4 u0 = q[0], u1 = q[1], u2 = q[2], u3 = q[3];
        const __half2* hA0 = (const __half2*)&u0;
        const __half2* hA1 = (const __half2*)&u1;
        const __half2* hB0 = (const __half2*)&u2;
        const __half2* hB1 = (const __half2*)&u3;
        #pragma unroll
        for (int i = 0; i < 4; i++) {
            float2 fa = __half22float2(hA0[i]);
            oA[2 * i]     += wA * fa.x;
            oA[2 * i + 1] += wA * fa.y;
            float2 fb = __half22float2(hB0[i]);
            oB[2 * i]     += wB * fb.x;
            oB[2 * i + 1] += wB * fb.y;
        }
        #pragma unroll
        for (int i = 0; i < 4; i++) {
            float2 fa = __half22float2(hA1[i]);
            oA[8 + 2 * i]     += wA * fa.x;
            oA[8 + 2 * i + 1] += wA * fa.y;
            float2 fb = __half22float2(hB1[i]);
            oB[8 + 2 * i]     += wB * fb.x;
            oB[8 + 2 * i + 1] += wB * fb.y;
        }
    }
}

__global__ void k_attn(const float* __restrict__ rpb)
{
    int idx = blockIdx.x * blockDim.x + threadIdx.x;  // 0 .. P*2-1
    int g = idx & 1;
    int p = idx >> 1;
    int b = p >> 12, hw = p & 4095;
    int bg = b * 2 + g;

    float q[32];
    const float4* qp = (const float4*)(g_qbuf + (size_t)p * CRC + g * 32);
    #pragma unroll
    for (int i = 0; i < 8; i++) {
        float4 t = qp[i];
        q[4 * i] = t.x * SCALEF; q[4 * i + 1] = t.y * SCALEF;
        q[4 * i + 2] = t.z * SCALEF; q[4 * i + 3] = t.w * SCALEF;
    }

    const float* off = g_offbuf + (size_t)(bg * HWP + hw) * OFFC;
    const __half* kb = g_kbufh + (size_t)bg * HWP * GCC;
    const __half* vb = g_vbufh + (size_t)bg * HWP * GCC;
    const float* rpA = rpb + (2 * g) * (N9 * HCC);
    const float* rpB = rpb + (2 * g + 1) * (N9 * HCC);

    int ix[N9], iy[N9];
    float fx[N9], fy[N9], lA[N9], lB[N9];

    #pragma unroll
    for (int n = 0; n < N9; n++) {
        float row = off[2 * n], col = off[2 * n + 1];
        float xf = floorf(col), yf = floorf(row);
        ix[n] = (int)xf; iy[n] = (int)yf;
        fx[n] = col - xf; fy[n] = row - yf;

        float w00 = (1.f - fx[n]) * (1.f - fy[n]);
        float w10 = fx[n] * (1.f - fy[n]);
        float w01 = (1.f - fx[n]) * fy[n];
        float w11 = fx[n] * fy[n];

        float s[32];
        #pragma unroll
        for (int i = 0; i < 32; i++) s[i] = 0.f;
        samp32(kb, iy[n],     ix[n],     w00, s);
        samp32(kb, iy[n],     ix[n] + 1, w10, s);
        samp32(kb, iy[n] + 1, ix[n],     w01, s);
        samp32(kb, iy[n] + 1, ix[n] + 1, w11, s);

        float a = 0.f, c2 = 0.f;
        const float* rA = rpA + n * HCC;
        const float* rB = rpB + n * HCC;
        #pragma unroll
        for (int i = 0; i < 16; i++) {
            a  += q[i]      * (s[i]      + rA[i]);
            c2 += q[16 + i] * (s[16 + i] + rB[i]);
        }
        lA[n] = a; lB[n] = c2;
    }

    float mA = lA[0], mB = lB[0];
    #pragma unroll
    for (int n = 1; n < N9; n++) { mA = fmaxf(mA, lA[n]); mB = fmaxf(mB, lB[n]); }
    float sA = 0.f, sB = 0.f;
    #pragma unroll
    for (int n = 0; n < N9; n++) {
        lA[n] = expf(lA[n] - mA); sA += lA[n];
        lB[n] = expf(lB[n] - mB); sB += lB[n];
    }
    float iA = 1.f / sA, iB = 1.f / sB;

    float oA[16], oB[16];
    #pragma unroll
    for (int i = 0; i < 16; i++) { oA[i] = 0.f; oB[i] = 0.f; }

    #pragma unroll
    for (int n = 0; n < N9; n++) {
        float wA = lA[n] * iA, wB = lB[n] * iB;
        float b00 = (1.f - fx[n]) * (1.f - fy[n]);
        float b10 = fx[n] * (1.f - fy[n]);
        float b01 = (1.f - fx[n]) * fy[n];
        float b11 = fx[n] * fy[n];
        samp32w2(vb, iy[n],     ix[n],     b00 * wA, b00 * wB, oA, oB);
        samp32w2(vb, iy[n],     ix[n] + 1, b10 * wA, b10 * wB, oA, oB);
        samp32w2(vb, iy[n] + 1, ix[n],     b01 * wA, b01 * wB, oA, oB);
        samp32w2(vb, iy[n] + 1, ix[n] + 1, b11 * wA, b11 * wB, oA, oB);
    }

    float* dst = g_attnout + (size_t)p * CRC + g * 32;
    #pragma unroll
    for (int i = 0; i < 4; i++)
        ((float4*)dst)[i] = make_float4(oA[4 * i], oA[4 * i + 1], oA[4 * i + 2], oA[4 * i + 3]);
    #pragma unroll
    for (int i = 0; i < 4; i++)
        ((float4*)dst)[4 + i] = make_float4(oB[4 * i], oB[4 * i + 1], oB[4 * i + 2], oB[4 * i + 3]);
}

// ---------------- launch ----------------
extern "C" void kernel_launch(void* const* d_in, const int* in_sizes, int n_in,
                              void* d_out, int out_size)
{
    const float* x      = (const float*)d_in[0];
    const float* offset = (const float*)d_in[1];
    const float* ln1_g  = (const float*)d_in[2];
    const float* ln1_b  = (const float*)d_in[3];
    const float* w_qkv  = (const float*)d_in[4];
    const float* w_dw   = (const float*)d_in[5];
    const float* ln2_g  = (const float*)d_in[6];
    const float* ln2_b  = (const float*)d_in[7];
    const float* w_off  = (const float*)d_in[8];
    const float* b_off  = (const float*)d_in[9];
    const float* rpb    = (const float*)d_in[10];
    const float* w_proj = (const float*)d_in[11];
    const float* b_proj = (const float*)d_in[12];
    const float* w_cls  = (const float*)d_in[13];
    const float* b_cls  = (const float*)d_in[14];
    float* out = (float*)d_out;

    const int dwSmem  = 3168 * 16;
    const int offSmem = 2112 * 16 + 5184 * 4;
    static int configured = 0;
    if (!configured) {
        cudaFuncSetAttribute(k_dw,  cudaFuncAttributeMaxDynamicSharedMemorySize, dwSmem);
        cudaFuncSetAttribute(k_off, cudaFuncAttributeMaxDynamicSharedMemorySize, offSmem);
        configured = 1;
    }

    k_ln<<<PP / 32, 256>>>(x, ln1_g, ln1_b);
    k_gemm0<<<dim3(3, PP / 128), 256>>>(w_qkv);
    k_dw<<<16 * 16, 256, dwSmem>>>(w_dw, ln2_g, ln2_b);
    k_off<<<16 * 32, 256, offSmem>>>(w_off, b_off, offset);
    k_attn<<<(PP * 2) / 128, 128>>>(rpb);
    k_gemm<1><<<dim3(4, PP / 128), 256>>>(w_proj, b_proj, x, nullptr);
    k_gemm<2><<<dim3(2, PP / 128), 256>>>(w_cls, b_cls, nullptr, out);
}

// round 10
// speedup vs baseline: 1.0481x; 1.0481x over previous
#include <cuda_runtime.h>
#include <cuda_bf16.h>
#include <cuda_fp16.h>
#include <math.h>

// ---------------- static config ----------------
#define HWP   4096
#define PP    32768
#define DIMC  256
#define CRC   64
#define GCC   32
#define HCC   16
#define N9    9
#define OFFC  18
#define NCLS  80
#define SCALEF 0.25f
#define MULF  5.0f

// ---------------- scratch ----------------
__device__ __nv_bfloat16 g_xnh[PP * DIMC];   // LN'd x, bf16 hi  [P,256]
__device__ __nv_bfloat16 g_xnl[PP * DIMC];   // LN'd x, bf16 lo
__device__ float  g_qbuf[PP * CRC];
__device__ __half g_kbufh[16 * HWP * GCC];
__device__ __half g_vbufh[16 * HWP * GCC];
__device__ float  g_tbuf[16 * HWP * GCC];
__device__ float  g_offbuf[16 * HWP * OFFC];
__device__ float  g_attnout[PP * CRC];
__device__ float  g_ybuf[PP * DIMC];

// ---------------- kernel 1: channel-LN + transpose + bf16 hi/lo split ----------
__global__ void k_ln(const float* __restrict__ x,
                     const float* __restrict__ gam,
                     const float* __restrict__ bet)
{
    __shared__ float s[DIMC][33];
    __shared__ float red[2][8][32];
    __shared__ float smean[32], srstd[32];

    int p0 = blockIdx.x * 32;
    int b  = p0 >> 12;
    int hw0 = p0 & 4095;
    int tid = threadIdx.x;
    int tx = tid & 31, ty = tid >> 5;

    const float* xb = x + (size_t)b * DIMC * HWP + hw0;
    for (int c = ty; c < DIMC; c += 8)
        s[c][tx] = xb[c * HWP + tx];
    __syncthreads();

    float sum = 0.f, sq = 0.f;
    for (int c = ty; c < DIMC; c += 8) {
        float v = s[c][tx];
        sum += v; sq += v * v;
    }
    red[0][ty][tx] = sum; red[1][ty][tx] = sq;
    __syncthreads();
    if (ty == 0) {
        float s1 = 0.f, s2 = 0.f;
        #pragma unroll
        for (int j = 0; j < 8; j++) { s1 += red[0][j][tx]; s2 += red[1][j][tx]; }
        float m = s1 * (1.f / 256.f);
        float v = s2 * (1.f / 256.f) - m * m;
        smean[tx] = m;
        srstd[tx] = rsqrtf(v + 1e-5f);
    }
    __syncthreads();

    float gg = gam[tid], bb = bet[tid];
    for (int pl = 0; pl < 32; pl++) {
        float v = (s[tid][pl] - smean[pl]) * srstd[pl] * gg + bb;
        __nv_bfloat16 h = __float2bfloat16(v);
        __nv_bfloat16 l = __float2bfloat16(v - __bfloat162float(h));
        size_t o = (size_t)(p0 + pl) * DIMC + tid;
        g_xnh[o] = h;
        g_xnl[o] = l;
    }
}

// ---------------- helpers ----------------
__device__ __forceinline__ void cvt_pair(float x0, float x1,
                                         unsigned& hi, unsigned& lo)
{
    __nv_bfloat16 h0 = __float2bfloat16(x0);
    __nv_bfloat16 h1 = __float2bfloat16(x1);
    float r0 = x0 - __bfloat162float(h0);
    float r1 = x1 - __bfloat162float(h1);
    __nv_bfloat16 l0 = __float2bfloat16(r0);
    __nv_bfloat16 l1 = __float2bfloat16(r1);
    unsigned short u0 = *(unsigned short*)&h0, u1 = *(unsigned short*)&h1;
    unsigned short v0 = *(unsigned short*)&l0, v1 = *(unsigned short*)&l1;
    hi = (unsigned)u0 | ((unsigned)u1 << 16);
    lo = (unsigned)v0 | ((unsigned)v1 << 16);
}

__device__ __forceinline__ void mma_bf16_v(float* c,
                                           unsigned a0, unsigned a1, unsigned a2, unsigned a3,
                                           unsigned b0, unsigned b1)
{
    asm volatile(
        "mma.sync.aligned.m16n8k16.row.col.f32.bf16.bf16.f32 "
        "{%0,%1,%2,%3}, {%4,%5,%6,%7}, {%8,%9}, {%0,%1,%2,%3};\n"
        : "+f"(c[0]), "+f"(c[1]), "+f"(c[2]), "+f"(c[3])
        : "r"(a0), "r"(a1), "r"(a2), "r"(a3), "r"(b0), "r"(b1));
}
#define MMA_BF16 mma_bf16_v

// ---------------- GEMM 0: qkv from pre-split A ------------------------------
__global__ void __launch_bounds__(256) k_gemm0(const float* __restrict__ Bw)
{
    constexpr int K = 256, Ntot = 192;

    __shared__ unsigned Ah[128][20], Al[128][20];
    __shared__ unsigned Bh[64][20],  Bl[64][20];

    int tid = threadIdx.x;
    int lane = tid & 31;
    int warpId = tid >> 5;
    int warpM = warpId & 3;
    int warpN = warpId >> 2;
    int row0 = blockIdx.y * 128, col0 = blockIdx.x * 64;

    float acc[2][4][4];
    #pragma unroll
    for (int mt = 0; mt < 2; mt++)
        #pragma unroll
        for (int nt = 0; nt < 4; nt++)
            #pragma unroll
            for (int e = 0; e < 4; e++) acc[mt][nt][e] = 0.f;

    uint4 ph[2], pl[2];
    float4 pb[2];

    #pragma unroll
    for (int i = 0; i < 2; i++) {
        int id = tid + i * 256;
        int row = id >> 2, fq = id & 3;
        ph[i] = *(const uint4*)(g_xnh + (size_t)(row0 + row) * K + fq * 8);
        pl[i] = *(const uint4*)(g_xnl + (size_t)(row0 + row) * K + fq * 8);
        int brow = id >> 3, bf = id & 7;
        pb[i] = make_float4(0.f, 0.f, 0.f, 0.f);
        if (col0 + brow < Ntot)
            pb[i] = *(const float4*)(Bw + (size_t)(col0 + brow) * K + bf * 4);
    }

    for (int k0 = 0; k0 < K; k0 += 32) {
        #pragma unroll
        for (int i = 0; i < 2; i++) {
            int id = tid + i * 256;
            int row = id >> 2, fq = id & 3;
            *(uint4*)&Ah[row][fq * 4] = ph[i];
            *(uint4*)&Al[row][fq * 4] = pl[i];
            int brow = id >> 3, bf = id & 7;
            unsigned h0, l0, h1, l1;
            float4 v = pb[i];
            cvt_pair(v.x, v.y, h0, l0);
            cvt_pair(v.z, v.w, h1, l1);
            Bh[brow][bf * 2] = h0; Bh[brow][bf * 2 + 1] = h1;
            Bl[brow][bf * 2] = l0; Bl[brow][bf * 2 + 1] = l1;
        }
        __syncthreads();

        if (k0 + 32 < K) {
            #pragma unroll
            for (int i = 0; i < 2; i++) {
                int id = tid + i * 256;
                int row = id >> 2, fq = id & 3;
                ph[i] = *(const uint4*)(g_xnh + (size_t)(row0 + row) * K + (k0 + 32) + fq * 8);
                pl[i] = *(const uint4*)(g_xnl + (size_t)(row0 + row) * K + (k0 + 32) + fq * 8);
                int brow = id >> 3, bf = id & 7;
                pb[i] = make_float4(0.f, 0.f, 0.f, 0.f);
                if (col0 + brow < Ntot)
                    pb[i] = *(const float4*)(Bw + (size_t)(col0 + brow) * K + (k0 + 32) + bf * 4);
            }
        }

        #pragma unroll
        for (int kk = 0; kk < 2; kk++) {
            int kb = kk * 8 + (lane & 3);
            unsigned ah[2][4], al[2][4];
            #pragma unroll
            for (int mt = 0; mt < 2; mt++) {
                int ar = warpM * 32 + mt * 16 + (lane >> 2);
                ah[mt][0] = Ah[ar][kb];     ah[mt][1] = Ah[ar + 8][kb];
                ah[mt][2] = Ah[ar][kb + 4]; ah[mt][3] = Ah[ar + 8][kb + 4];
                al[mt][0] = Al[ar][kb];     al[mt][1] = Al[ar + 8][kb];
                al[mt][2] = Al[ar][kb + 4]; al[mt][3] = Al[ar + 8][kb + 4];
            }
            #pragma unroll
            for (int nt = 0; nt < 4; nt++) {
                int br = warpN * 32 + nt * 8 + (lane >> 2);
                unsigned bh0 = Bh[br][kb], bh1 = Bh[br][kb + 4];
                unsigned bl0 = Bl[br][kb], bl1 = Bl[br][kb + 4];
                #pragma unroll
                for (int mt = 0; mt < 2; mt++) {
                    MMA_BF16(acc[mt][nt], ah[mt][0], ah[mt][1], ah[mt][2], ah[mt][3], bh0, bh1);
                    MMA_BF16(acc[mt][nt], ah[mt][0], ah[mt][1], ah[mt][2], ah[mt][3], bl0, bl1);
                    MMA_BF16(acc[mt][nt], al[mt][0], al[mt][1], al[mt][2], al[mt][3], bh0, bh1);
                }
            }
        }
        __syncthreads();
    }

    #pragma unroll
    for (int mt = 0; mt < 2; mt++) {
        #pragma unroll
        for (int nt = 0; nt < 4; nt++) {
            #pragma unroll
            for (int e = 0; e < 4; e++) {
                int p = row0 + warpM * 32 + mt * 16 + (lane >> 2) + ((e >= 2) ? 8 : 0);
                int o = col0 + warpN * 32 + nt * 8 + 2 * (lane & 3) + (e & 1);
                float v = acc[mt][nt][e];
                int bidx = p >> 12, hw = p & 4095;
                if (o < 64) {
                    g_qbuf[p * 64 + o] = v;
                } else if (o < 128) {
                    int c = o - 64;
                    g_kbufh[((size_t)(bidx * 2 + (c >> 5)) * HWP + hw) * GCC + (c & 31)] =
                        __float2half(v);
                } else {
                    int c = o - 128;
                    g_vbufh[((size_t)(bidx * 2 + (c >> 5)) * HWP + hw) * GCC + (c & 31)] =
                        __float2half(v);
                }
            }
        }
    }
}

// ---------------- GEMM modes 1/2 (fp32 A, cvt staging + prefetch) --------------
template<int MODE>
__global__ void __launch_bounds__(256) k_gemm(const float* __restrict__ Bw,
                                              const float* __restrict__ bias,
                                              const float* __restrict__ resid,
                                              float* __restrict__ outp)
{
    constexpr int K    = (MODE == 1) ? 64 : 256;
    constexpr int Ntot = (MODE == 1) ? 256 : 80;
    const float* A = (MODE == 1) ? g_attnout : g_ybuf;

    __shared__ unsigned Ah[128][20], Al[128][20];
    __shared__ unsigned Bh[64][20],  Bl[64][20];

    int tid = threadIdx.x;
    int lane = tid & 31;
    int warpId = tid >> 5;
    int warpM = warpId & 3;
    int warpN = warpId >> 2;
    int row0 = blockIdx.y * 128, col0 = blockIdx.x * 64;

    float acc[2][4][4];
    #pragma unroll
    for (int mt = 0; mt < 2; mt++)
        #pragma unroll
        for (int nt = 0; nt < 4; nt++)
            #pragma unroll
            for (int e = 0; e < 4; e++) acc[mt][nt][e] = 0.f;

    float4 pa[4], pb[2];
    #pragma unroll
    for (int i = 0; i < 4; i++) {
        int id = tid + i * 256;
        int row = id >> 3, f = id & 7;
        pa[i] = *(const float4*)(A + (size_t)(row0 + row) * K + f * 4);
    }
    #pragma unroll
    for (int i = 0; i < 2; i++) {
        int id = tid + i * 256;
        int row = id >> 3, f = id & 7;
        pb[i] = make_float4(0.f, 0.f, 0.f, 0.f);
        if (col0 + row < Ntot)
            pb[i] = *(const float4*)(Bw + (size_t)(col0 + row) * K + f * 4);
    }

    for (int k0 = 0; k0 < K; k0 += 32) {
        #pragma unroll
        for (int i = 0; i < 4; i++) {
            int id = tid + i * 256;
            int row = id >> 3, f = id & 7;
            unsigned h0, l0, h1, l1;
            cvt_pair(pa[i].x, pa[i].y, h0, l0);
            cvt_pair(pa[i].z, pa[i].w, h1, l1);
            Ah[row][f * 2] = h0; Ah[row][f * 2 + 1] = h1;
            Al[row][f * 2] = l0; Al[row][f * 2 + 1] = l1;
        }
        #pragma unroll
        for (int i = 0; i < 2; i++) {
            int id = tid + i * 256;
            int row = id >> 3, f = id & 7;
            unsigned h0, l0, h1, l1;
            cvt_pair(pb[i].x, pb[i].y, h0, l0);
            cvt_pair(pb[i].z, pb[i].w, h1, l1);
            Bh[row][f * 2] = h0; Bh[row][f * 2 + 1] = h1;
            Bl[row][f * 2] = l0; Bl[row][f * 2 + 1] = l1;
        }
        __syncthreads();

        if (k0 + 32 < K) {
            #pragma unroll
            for (int i = 0; i < 4; i++) {
                int id = tid + i * 256;
                int row = id >> 3, f = id & 7;
                pa[i] = *(const float4*)(A + (size_t)(row0 + row) * K + (k0 + 32) + f * 4);
            }
            #pragma unroll
            for (int i = 0; i < 2; i++) {
                int id = tid + i * 256;
                int row = id >> 3, f = id & 7;
                pb[i] = make_float4(0.f, 0.f, 0.f, 0.f);
                if (col0 + row < Ntot)
                    pb[i] = *(const float4*)(Bw + (size_t)(col0 + row) * K + (k0 + 32) + f * 4);
            }
        }

        #pragma unroll
        for (int kk = 0; kk < 2; kk++) {
            int kb = kk * 8 + (lane & 3);
            unsigned ah[2][4], al[2][4];
            #pragma unroll
            for (int mt = 0; mt < 2; mt++) {
                int ar = warpM * 32 + mt * 16 + (lane >> 2);
                ah[mt][0] = Ah[ar][kb];     ah[mt][1] = Ah[ar + 8][kb];
                ah[mt][2] = Ah[ar][kb + 4]; ah[mt][3] = Ah[ar + 8][kb + 4];
                al[mt][0] = Al[ar][kb];     al[mt][1] = Al[ar + 8][kb];
                al[mt][2] = Al[ar][kb + 4]; al[mt][3] = Al[ar + 8][kb + 4];
            }
            #pragma unroll
            for (int nt = 0; nt < 4; nt++) {
                int br = warpN * 32 + nt * 8 + (lane >> 2);
                unsigned bh0 = Bh[br][kb], bh1 = Bh[br][kb + 4];
                unsigned bl0 = Bl[br][kb], bl1 = Bl[br][kb + 4];
                #pragma unroll
                for (int mt = 0; mt < 2; mt++) {
                    MMA_BF16(acc[mt][nt], ah[mt][0], ah[mt][1], ah[mt][2], ah[mt][3], bh0, bh1);
                    MMA_BF16(acc[mt][nt], ah[mt][0], ah[mt][1], ah[mt][2], ah[mt][3], bl0, bl1);
                    MMA_BF16(acc[mt][nt], al[mt][0], al[mt][1], al[mt][2], al[mt][3], bh0, bh1);
                }
            }
        }
        __syncthreads();
    }

    #pragma unroll
    for (int mt = 0; mt < 2; mt++) {
        #pragma unroll
        for (int nt = 0; nt < 4; nt++) {
            #pragma unroll
            for (int e = 0; e < 4; e++) {
                int p = row0 + warpM * 32 + mt * 16 + (lane >> 2) + ((e >= 2) ? 8 : 0);
                int o = col0 + warpN * 32 + nt * 8 + 2 * (lane & 3) + (e & 1);
                float v = acc[mt][nt][e];
                int bidx = p >> 12, hw = p & 4095;
                if (MODE == 1) {
                    g_ybuf[(size_t)p * DIMC + o] =
                        v + bias[o] + resid[(size_t)bidx * DIMC * HWP + o * HWP + hw];
                } else {
                    if (o < Ntot)
                        outp[(size_t)bidx * NCLS * HWP + o * HWP + hw] = v + bias[o];
                }
            }
        }
    }
}

// ---------------- kernel 3: smem-tiled depthwise 3x3 + LN(32) + GELU ----------
__global__ void __launch_bounds__(256, 2) k_dw(const float* __restrict__ wdw,
                                               const float* __restrict__ g2,
                                               const float* __restrict__ b2)
{
    extern __shared__ float4 st4[];
    __shared__ float sw[GCC * 9];
    __shared__ float sg[GCC], sb[GCC];

    int bg = blockIdx.x >> 4;
    int h0 = (blockIdx.x & 15) * 4;
    int b = bg >> 1, g = bg & 1;
    int tid = threadIdx.x;

    for (int i = tid; i < GCC * 9; i += 256) sw[i] = wdw[i];
    if (tid < GCC) { sg[tid] = g2[tid]; sb[tid] = b2[tid]; }
    for (int i = tid; i < 3168; i += 256) st4[i] = make_float4(0.f, 0.f, 0.f, 0.f);
    __syncthreads();

    for (int i = tid; i < 3072; i += 256) {
        int c4 = i & 7, col = (i >> 3) & 63, r = i >> 9;
        int gr = h0 - 1 + r;
        if ((unsigned)gr < 64u)
            st4[(c4 * 6 + r) * 66 + col + 1] =
                *(const float4*)(g_qbuf + ((size_t)(b * HWP + gr * 64 + col)) * CRC + g * GCC + c4 * 4);
    }
    __syncthreads();

    int col = tid & 63;
    int row = tid >> 6;
    int h = h0 + row;

    float acc[GCC];
    #pragma unroll
    for (int c = 0; c < GCC; c++) acc[c] = 0.f;

    #pragma unroll
    for (int ky = 0; ky < 3; ky++) {
        #pragma unroll
        for (int kx = 0; kx < 3; kx++) {
            int kidx = ky * 3 + kx;
            #pragma unroll
            for (int c4 = 0; c4 < 8; c4++) {
                float4 v = st4[(c4 * 6 + row + ky) * 66 + col + kx];
                acc[c4 * 4 + 0] += v.x * sw[(c4 * 4 + 0) * 9 + kidx];
                acc[c4 * 4 + 1] += v.y * sw[(c4 * 4 + 1) * 9 + kidx];
                acc[c4 * 4 + 2] += v.z * sw[(c4 * 4 + 2) * 9 + kidx];
                acc[c4 * 4 + 3] += v.w * sw[(c4 * 4 + 3) * 9 + kidx];
            }
        }
    }

    float m = 0.f;
    #pragma unroll
    for (int c = 0; c < GCC; c++) m += acc[c];
    m *= (1.f / GCC);
    float v = 0.f;
    #pragma unroll
    for (int c = 0; c < GCC; c++) { float d = acc[c] - m; v += d * d; }
    float rs = rsqrtf(v * (1.f / GCC) + 1e-5f);

    float* dst = g_tbuf + ((size_t)bg * HWP + h * 64 + col) * GCC;
    #pragma unroll
    for (int c = 0; c < GCC; c++) {
        float t = (acc[c] - m) * rs * sg[c] + sb[c];
        dst[c] = 0.5f * t * (1.f + erff(t * 0.70710678118654752f));
    }
}

// ---------------- kernel 4: smem-tiled 3x3 conv (32->18), 2 rows/block --------
__global__ void __launch_bounds__(256) k_off(const float* __restrict__ woff,
                                             const float* __restrict__ boff,
                                             const float* __restrict__ offset)
{
    extern __shared__ float4 dyn4[];
    float4* st4 = dyn4;
    float*  sw  = (float*)(dyn4 + 2112);
    float4* sw4 = (float4*)sw;

    int bg = blockIdx.x >> 5;
    int h0 = (blockIdx.x & 31) * 2;
    int tid = threadIdx.x;

    for (int i = tid; i < OFFC * GCC * 9; i += 256) {
        int o = i / (GCC * 9); int rem = i - o * (GCC * 9);
        int c = rem / 9; int kidx = rem - c * 9;
        sw[(kidx * OFFC + o) * GCC + c] = woff[i];
    }
    for (int i = tid; i < 2112; i += 256) st4[i] = make_float4(0.f, 0.f, 0.f, 0.f);
    __syncthreads();

    for (int i = tid; i < 2048; i += 256) {
        int c4 = i & 7, col = (i >> 3) & 63, r = i >> 9;
        int gr = h0 - 1 + r;
        if ((unsigned)gr < 64u)
            st4[(c4 * 4 + r) * 66 + col + 1] =
                *(const float4*)(g_tbuf + ((size_t)(bg * HWP + gr * 64 + col)) * GCC + c4 * 4);
    }
    __syncthreads();

    int col = tid & 63;
    int og  = (tid >> 6) & 1;
    int row = tid >> 7;
    int h = h0 + row;
    int b = bg >> 1;

    float acc[9];
    #pragma unroll
    for (int o = 0; o < 9; o++) acc[o] = boff[og * 9 + o];

    #pragma unroll
    for (int c4 = 0; c4 < 8; c4++) {
        #pragma unroll
        for (int ky = 0; ky < 3; ky++) {
            const float4* trow = &st4[(c4 * 4 + row + ky) * 66];
            float4 t[3];
            t[0] = trow[col]; t[1] = trow[col + 1]; t[2] = trow[col + 2];
            #pragma unroll
            for (int kx = 0; kx < 3; kx++) {
                int kidx = ky * 3 + kx;
                #pragma unroll
                for (int o = 0; o < 9; o++) {
                    float4 w = sw4[(kidx * OFFC + og * 9 + o) * 8 + c4];
                    acc[o] += t[kx].x * w.x + t[kx].y * w.y +
                              t[kx].z * w.z + t[kx].w * w.w;
                }
            }
        }
    }

    int hw = h * 64 + col;
    const float* ofs = offset + (size_t)b * OFFC * HWP + hw;
    float* dst = g_offbuf + ((size_t)bg * HWP + hw) * OFFC + og * 9;
    #pragma unroll
    for (int o = 0; o < 9; o++)
        dst[o] = tanhf(acc[o]) * MULF + ofs[(og * 9 + o) * HWP];
}

// ---------------- kernel 5: deformable gather + softmax attention (fp16 k/v) ---
__device__ __forceinline__ void samp16h(const __half* __restrict__ bufh,
                                        int y, int x, float w, float s[16])
{
    if ((unsigned)x < 64u && (unsigned)y < 64u) {
        const uint4* q = (const uint4*)(bufh + (y * 64 + x) * GCC);
        uint4 u0 = q[0], u1 = q[1];
        const __half2* h0 = (const __half2*)&u0;
        const __half2* h1 = (const __half2*)&u1;
        #pragma unroll
        for (int i = 0; i < 4; i++) {
            float2 f = __half22float2(h0[i]);
            s[2 * i]     += w * f.x;
            s[2 * i + 1] += w * f.y;
        }
        #pragma unroll
        for (int i = 0; i < 4; i++) {
            float2 f = __half22float2(h1[i]);
            s[8 + 2 * i]     += w * f.x;
            s[8 + 2 * i + 1] += w * f.y;
        }
    }
}

__global__ void k_attn(const float* __restrict__ rpb)
{
    int idx = blockIdx.x * blockDim.x + threadIdx.x;
    int nh = idx & 3;
    int p  = idx >> 2;
    int b = p >> 12, hw = p & 4095;
    int g = nh >> 1, hb = (nh & 1) * 16;
    int bg = b * 2 + g;

    float q[16];
    const float* qp = g_qbuf + (size_t)p * CRC + nh * HCC;
    #pragma unroll
    for (int i = 0; i < 16; i++) q[i] = qp[i] * SCALEF;

    const float* off = g_offbuf + (size_t)(bg * HWP + hw) * OFFC;
    const __half* kb = g_kbufh + (size_t)bg * HWP * GCC + hb;
    const __half* vb = g_vbufh + (size_t)bg * HWP * GCC + hb;
    const float* rp = rpb + nh * (N9 * HCC);

    int ix[N9], iy[N9];
    float fx[N9], fy[N9], logit[N9];

    #pragma unroll
    for (int n = 0; n < N9; n++) {
        float row = off[2 * n], col = off[2 * n + 1];
        float xf = floorf(col), yf = floorf(row);
        ix[n] = (int)xf; iy[n] = (int)yf;
        fx[n] = col - xf; fy[n] = row - yf;

        float w00 = (1.f - fx[n]) * (1.f - fy[n]);
        float w10 = fx[n] * (1.f - fy[n]);
        float w01 = (1.f - fx[n]) * fy[n];
        float w11 = fx[n] * fy[n];

        float s[16];
        #pragma unroll
        for (int i = 0; i < 16; i++) s[i] = 0.f;
        samp16h(kb, iy[n],     ix[n],     w00, s);
        samp16h(kb, iy[n],     ix[n] + 1, w10, s);
        samp16h(kb, iy[n] + 1, ix[n],     w01, s);
        samp16h(kb, iy[n] + 1, ix[n] + 1, w11, s);

        float l = 0.f;
        const float* rpn = rp + n * HCC;
        #pragma unroll
        for (int i = 0; i < 16; i++) l += q[i] * (s[i] + rpn[i]);
        logit[n] = l;
    }

    float mx = logit[0];
    #pragma unroll
    for (int n = 1; n < N9; n++) mx = fmaxf(mx, logit[n]);
    float sum = 0.f;
    #pragma unroll
    for (int n = 0; n < N9; n++) { logit[n] = expf(logit[n] - mx); sum += logit[n]; }
    float inv = 1.f / sum;

    float o16[16];
    #pragma unroll
    for (int i = 0; i < 16; i++) o16[i] = 0.f;

    #pragma unroll
    for (int n = 0; n < N9; n++) {
        float wn = logit[n] * inv;
        float w00 = (1.f - fx[n]) * (1.f - fy[n]) * wn;
        float w10 = fx[n] * (1.f - fy[n]) * wn;
        float w01 = (1.f - fx[n]) * fy[n] * wn;
        float w11 = fx[n] * fy[n] * wn;
        samp16h(vb, iy[n],     ix[n],     w00, o16);
        samp16h(vb, iy[n],     ix[n] + 1, w10, o16);
        samp16h(vb, iy[n] + 1, ix[n],     w01, o16);
        samp16h(vb, iy[n] + 1, ix[n] + 1, w11, o16);
    }

    float* dst = g_attnout + (size_t)p * CRC + nh * HCC;
    #pragma unroll
    for (int i = 0; i < 16; i++) dst[i] = o16[i];
}

// ---------------- launch ----------------
extern "C" void kernel_launch(void* const* d_in, const int* in_sizes, int n_in,
                              void* d_out, int out_size)
{
    const float* x      = (const float*)d_in[0];
    const float* offset = (const float*)d_in[1];
    const float* ln1_g  = (const float*)d_in[2];
    const float* ln1_b  = (const float*)d_in[3];
    const float* w_qkv  = (const float*)d_in[4];
    const float* w_dw   = (const float*)d_in[5];
    const float* ln2_g  = (const float*)d_in[6];
    const float* ln2_b  = (const float*)d_in[7];
    const float* w_off  = (const float*)d_in[8];
    const float* b_off  = (const float*)d_in[9];
    const float* rpb    = (const float*)d_in[10];
    const float* w_proj = (const float*)d_in[11];
    const float* b_proj = (const float*)d_in[12];
    const float* w_cls  = (const float*)d_in[13];
    const float* b_cls  = (const float*)d_in[14];
    float* out = (float*)d_out;

    const int dwSmem  = 3168 * 16;
    const int offSmem = 2112 * 16 + 5184 * 4;
    static int configured = 0;
    if (!configured) {
        cudaFuncSetAttribute(k_dw,  cudaFuncAttributeMaxDynamicSharedMemorySize, dwSmem);
        cudaFuncSetAttribute(k_off, cudaFuncAttributeMaxDynamicSharedMemorySize, offSmem);
        configured = 1;
    }

    k_ln<<<PP / 32, 256>>>(x, ln1_g, ln1_b);
    k_gemm0<<<dim3(3, PP / 128), 256>>>(w_qkv);
    k_dw<<<16 * 16, 256, dwSmem>>>(w_dw, ln2_g, ln2_b);
    k_off<<<16 * 32, 256, offSmem>>>(w_off, b_off, offset);
    k_attn<<<(PP * 4) / 128, 128>>>(rpb);
    k_gemm<1><<<dim3(4, PP / 128), 256>>>(w_proj, b_proj, x, nullptr);
    k_gemm<2><<<dim3(2, PP / 128), 256>>>(w_cls, b_cls, nullptr, out);
}